// round 2
// baseline (speedup 1.0000x reference)
#include <cuda_runtime.h>

#define FULL_MASK 0xffffffffu
typedef unsigned long long ull;

// ---- f32x2 packed-math helpers (sm_103a FFMA2 path; ptxas won't auto-fuse) ----
__device__ __forceinline__ ull pk2(float lo, float hi) {
    ull r; asm("mov.b64 %0,{%1,%2};" : "=l"(r) : "f"(lo), "f"(hi)); return r;
}
__device__ __forceinline__ void up2(ull v, float& lo, float& hi) {
    asm("mov.b64 {%0,%1},%2;" : "=f"(lo), "=f"(hi) : "l"(v));
}
__device__ __forceinline__ ull fma2(ull a, ull b, ull c) {
    ull d; asm("fma.rn.f32x2 %0,%1,%2,%3;" : "=l"(d) : "l"(a), "l"(b), "l"(c)); return d;
}
__device__ __forceinline__ ull mul2(ull a, ull b) {
    ull d; asm("mul.rn.f32x2 %0,%1,%2;" : "=l"(d) : "l"(a), "l"(b)); return d;
}
__device__ __forceinline__ ull add2(ull a, ull b) {
    ull d; asm("add.rn.f32x2 %0,%1,%2;" : "=l"(d) : "l"(a), "l"(b)); return d;
}

// Forward-Euler ScaledODENet, one warp per batch element.
//
// State reformulation: instead of carrying ys (16) and recomputing
// a = b1 + x*w0 + W1s^T ys each step, carry u = W1s^T ys directly:
//   u(t+1) = u(t) + W1s^T d(t) + c,   c = W1s^T (b2/sr)  (precomputed)
//   a(t)   = u(t) + x_t * w0 + b1
// d(t) (without the b2 term) is produced by a 5-round warp butterfly
// allreduce of the per-lane W2 partials. Output channel ys[0] is kept as a
// separate scalar accumulator.
__global__ __launch_bounds__(32, 1)
void ode_fe_kernel(const float* __restrict__ x,
                   const float* __restrict__ W1,
                   const float* __restrict__ b1,
                   const float* __restrict__ b2,
                   const float* __restrict__ W2,
                   float* __restrict__ out,
                   int T) {
    constexpr int B = 32;
    const int b = blockIdx.x;
    const int l = threadIdx.x;            // lane: owns hidden units l, l+32
    const float inv_sr = 1.0f / 44100.0f;

    // ---- one-time weight staging (registers) ----
    const float w0lo = W1[l], w0hi = W1[l + 32];      // W1 row 0 (x input)
    const float b1lo = b1[l], b1hi = b1[l + 32];

    // W1 rows 1..16 (state rows), packed as (k even, k odd) pairs per unit
    ull w1lo2[8], w1hi2[8];
#pragma unroll
    for (int kp = 0; kp < 8; ++kp) {
        w1lo2[kp] = pk2(W1[(2 * kp + 1) * 64 + l],      W1[(2 * kp + 2) * 64 + l]);
        w1hi2[kp] = pk2(W1[(2 * kp + 1) * 64 + l + 32], W1[(2 * kp + 2) * 64 + l + 32]);
    }

    // W2 rows l, l+32 pre-scaled by 1/sr, packed over output-index pairs
    ull w2lo2[8], w2hi2[8];
#pragma unroll
    for (int kp = 0; kp < 8; ++kp) {
        w2lo2[kp] = pk2(W2[l * 16 + 2 * kp] * inv_sr,        W2[l * 16 + 2 * kp + 1] * inv_sr);
        w2hi2[kp] = pk2(W2[(l + 32) * 16 + 2 * kp] * inv_sr, W2[(l + 32) * 16 + 2 * kp + 1] * inv_sr);
    }

    // c = W1s^T (b2/sr), one scalar per owned hidden unit; seed packs (c, 0)
    float clo = 0.0f, chi = 0.0f;
#pragma unroll
    for (int j = 0; j < 16; ++j) {
        const float bj = b2[j] * inv_sr;
        clo = fmaf(bj, W1[(j + 1) * 64 + l],      clo);
        chi = fmaf(bj, W1[(j + 1) * 64 + l + 32], chi);
    }
    const ull clo2 = pk2(clo, 0.0f);
    const ull chi2 = pk2(chi, 0.0f);
    const ull zero2 = pk2(0.0f, 0.0f);
    const float b20s = b2[0] * inv_sr;     // output-channel bias增 per step

    // loop-carried state
    ull u2lo = zero2, u2hi = zero2;        // u split as (even-k sum, odd-k sum)
    float ys0 = 0.0f;                      // output channel accumulator

    if (l == 0) out[b] = 0.0f;             // out row t=0 is zeros
    const int nsteps = T - 1;

    // x prefetch: 32 timesteps per register, one block ahead
    float xbuf  = (l < nsteps)      ? x[l * B + b]        : 0.0f;
    float xnext = (l + 32 < nsteps) ? x[(l + 32) * B + b] : 0.0f;

    for (int t = 0; t < nsteps; ++t) {
        const float xt = __shfl_sync(FULL_MASK, xbuf, t & 31);

        // ---- a = u + x*w0 + b1 ----
        float ulx, uly, uhx, uhy;
        up2(u2lo, ulx, uly);
        up2(u2hi, uhx, uhy);
        const float alo = (ulx + uly) + fmaf(xt, w0lo, b1lo);
        const float ahi = (uhx + uhy) + fmaf(xt, w0hi, b1hi);

        // ---- tanh(a) = 1 - 2/(exp(2a)+1) ----
        const float elo = __expf(2.0f * alo);
        const float ehi = __expf(2.0f * ahi);
        const float hlo = 1.0f - __fdividef(2.0f, elo + 1.0f);
        const float hhi = 1.0f - __fdividef(2.0f, ehi + 1.0f);

        // ---- per-lane W2 partials (packed), unpacked into butterfly regs ----
        const ull h2lo = pk2(hlo, hlo);
        const ull h2hi = pk2(hhi, hhi);
        float v[16];
#pragma unroll
        for (int kp = 0; kp < 8; ++kp) {
            const ull p2 = fma2(h2lo, w2lo2[kp], mul2(h2hi, w2hi2[kp]));
            up2(p2, v[2 * kp], v[2 * kp + 1]);
        }

        // ---- 5-round butterfly allreduce: every lane ends with full d ----
#pragma unroll
        for (int off = 16; off > 0; off >>= 1) {
            float r[16];
#pragma unroll
            for (int k = 0; k < 16; ++k)
                r[k] = __shfl_xor_sync(FULL_MASK, v[k], off);
#pragma unroll
            for (int k = 0; k < 16; ++k)
                v[k] += r[k];
        }

        // ---- u += W1s^T d + c  (packed, two 4-deep chains per unit) ----
        ull d2[8];
#pragma unroll
        for (int kp = 0; kp < 8; ++kp)
            d2[kp] = pk2(v[2 * kp], v[2 * kp + 1]);

        ull sloA = fma2(d2[0], w1lo2[0], clo2);
        ull sloB = mul2(d2[4], w1lo2[4]);
        ull shiA = fma2(d2[0], w1hi2[0], chi2);
        ull shiB = mul2(d2[4], w1hi2[4]);
#pragma unroll
        for (int kp = 1; kp < 4; ++kp) {
            sloA = fma2(d2[kp],     w1lo2[kp],     sloA);
            sloB = fma2(d2[kp + 4], w1lo2[kp + 4], sloB);
            shiA = fma2(d2[kp],     w1hi2[kp],     shiA);
            shiB = fma2(d2[kp + 4], w1hi2[kp + 4], shiB);
        }
        u2lo = add2(u2lo, add2(sloA, sloB));
        u2hi = add2(u2hi, add2(shiA, shiB));

        // ---- output channel ----
        ys0 += v[0] + b20s;
        if (l == 0) out[(t + 1) * B + b] = ys0;

        // ---- refill x block-ahead buffer ----
        if ((t & 31) == 31) {
            xbuf = xnext;
            const int tn = t + 33 + l;
            xnext = (tn < nsteps) ? x[tn * B + b] : 0.0f;
        }
    }
}

extern "C" void kernel_launch(void* const* d_in, const int* in_sizes, int n_in,
                              void* d_out, int out_size) {
    const float* x  = (const float*)d_in[0];
    const float* W1 = (const float*)d_in[1];
    const float* b1 = (const float*)d_in[2];
    const float* W2 = (const float*)d_in[3];
    const float* b2 = (const float*)d_in[4];
    float* out = (float*)d_out;

    const int T = in_sizes[0] / 32;   // x is (T, B=32, F=1)
    ode_fe_kernel<<<32, 32>>>(x, W1, b1, b2, W2, out, T);
}

// round 3
// speedup vs baseline: 1.9166x; 1.9166x over previous
#include <cuda_runtime.h>

#define FULL_MASK 0xffffffffu
typedef unsigned long long ull;

// ---- f32x2 packed-math helpers ----
__device__ __forceinline__ ull pk2(float lo, float hi) {
    ull r; asm("mov.b64 %0,{%1,%2};" : "=l"(r) : "f"(lo), "f"(hi)); return r;
}
__device__ __forceinline__ void up2(ull v, float& lo, float& hi) {
    asm("mov.b64 {%0,%1},%2;" : "=f"(lo), "=f"(hi) : "l"(v));
}
__device__ __forceinline__ ull fma2(ull a, ull b, ull c) {
    ull d; asm("fma.rn.f32x2 %0,%1,%2,%3;" : "=l"(d) : "l"(a), "l"(b), "l"(c)); return d;
}
__device__ __forceinline__ ull mul2(ull a, ull b) {
    ull d; asm("mul.rn.f32x2 %0,%1,%2;" : "=l"(d) : "l"(a), "l"(b)); return d;
}
__device__ __forceinline__ ull add2(ull a, ull b) {
    ull d; asm("add.rn.f32x2 %0,%1,%2;" : "=l"(d) : "l"(a), "l"(b)); return d;
}
__device__ __forceinline__ float tanh_hw(float x) {
    float y; asm("tanh.approx.f32 %0, %1;" : "=f"(y) : "f"(x)); return y;
}

// Forward-Euler ScaledODENet, one warp per batch element.
//
// Recurrence carried as U = b1 + W1s^T ys (64-vec, 2 packed per lane):
//   a_t  = U_t + x_t * w0                      (per-lane packed FMA)
//   h_t  = tanh(a_t)                           (MUFU.TANH x2)
//   d_t  = (h_t @ W2)/sr                       (permuted reduce-scatter)
//   U    += sum_j d_j * W1col[j] + c           (16 indep broadcast FMAs)
//   ys0  += d_0 + b2[0]/sr                     (lane 0, off critical path)
//
// Reduce-scatter slot permutation: slot i of lane l holds the partial of
// d[i ^ (l & 15)]. Then every round is the lane-uniform
//   v[i] += shfl_xor(v[i+half], off)   for off = 8,4,2,1,16
// and lane l finishes with the complete d[l & 15].
__global__ __launch_bounds__(32, 1)
void ode_fe_kernel(const float* __restrict__ x,
                   const float* __restrict__ W1,
                   const float* __restrict__ b1,
                   const float* __restrict__ b2,
                   const float* __restrict__ W2,
                   float* __restrict__ out,
                   int T) {
    constexpr int B = 32;
    const int b = blockIdx.x;
    const int l = threadIdx.x;              // owns hidden units l, l+32
    const float inv_sr = 1.0f / 44100.0f;
    const int perm = l & 15;

    // ---- one-time weight staging ----
    const ull w02 = pk2(W1[l], W1[l + 32]);           // W1 row 0 (x weights)

    // W2 rows l, l+32 pre-scaled by 1/sr, loaded in RS-permuted slot order
    float w2lo[16], w2hi[16];
#pragma unroll
    for (int i = 0; i < 16; ++i) {
        const int j = i ^ perm;
        w2lo[i] = W2[l * 16 + j] * inv_sr;
        w2hi[i] = W2[(l + 32) * 16 + j] * inv_sr;
    }

    // W1 state columns, packed (row l, row l+32) per state index j
    ull w1c2[16];
#pragma unroll
    for (int j = 0; j < 16; ++j)
        w1c2[j] = pk2(W1[(j + 1) * 64 + l], W1[(j + 1) * 64 + l + 32]);

    // c = W1s^T (b2/sr), packed; seeds the broadcast FMA tree each step
    float clo = 0.0f, chi = 0.0f;
#pragma unroll
    for (int j = 0; j < 16; ++j) {
        const float bj = b2[j] * inv_sr;
        clo = fmaf(bj, W1[(j + 1) * 64 + l],      clo);
        chi = fmaf(bj, W1[(j + 1) * 64 + l + 32], chi);
    }
    const ull c2 = pk2(clo, chi);
    const float b20s = b2[0] * inv_sr;

    // ---- loop-carried state ----
    ull U2 = pk2(b1[l], b1[l + 32]);        // U = b1 + W1s^T ys  (ys starts 0)
    float ys0 = 0.0f;                       // output channel (lane 0)

    if (l == 0) out[b] = 0.0f;              // t=0 output row is zeros
    const int nsteps = T - 1;

    // x prefetch: 32 timesteps per register, one block ahead
    float xbuf  = (l < nsteps)      ? x[l * B + b]        : 0.0f;
    float xnext = (l + 32 < nsteps) ? x[(l + 32) * B + b] : 0.0f;
    float xt = __shfl_sync(FULL_MASK, xbuf, 0);

#pragma unroll 1
    for (int t = 0; t < nsteps; ++t) {
        // ---- a = U + x*w0 ; h = tanh(a) ----
        const ull a2 = fma2(pk2(xt, xt), w02, U2);
        float alo, ahi;
        up2(a2, alo, ahi);
        const float hlo = tanh_hw(alo);
        const float hhi = tanh_hw(ahi);

        // ---- per-lane W2 partials in permuted slots ----
        float v[16];
#pragma unroll
        for (int i = 0; i < 16; ++i)
            v[i] = fmaf(hlo, w2lo[i], hhi * w2hi[i]);

        // refill / prefetch next xt (independent of the reduction below)
        if ((t & 31) == 31) {
            xbuf = xnext;
            const int tn = t + 33 + l;
            xnext = (tn < nsteps) ? x[tn * B + b] : 0.0f;
        }
        xt = __shfl_sync(FULL_MASK, xbuf, (t + 1) & 31);

        // ---- permuted reduce-scatter: lane l ends with d[l & 15] ----
#pragma unroll
        for (int i = 0; i < 8; ++i) v[i] += __shfl_xor_sync(FULL_MASK, v[i + 8], 8);
#pragma unroll
        for (int i = 0; i < 4; ++i) v[i] += __shfl_xor_sync(FULL_MASK, v[i + 4], 4);
#pragma unroll
        for (int i = 0; i < 2; ++i) v[i] += __shfl_xor_sync(FULL_MASK, v[i + 2], 2);
        v[0] += __shfl_xor_sync(FULL_MASK, v[1], 1);
        v[0] += __shfl_xor_sync(FULL_MASK, v[0], 16);

        // ---- output channel (lane 0; latency overlaps next step) ----
        ys0 += v[0] + b20s;
        if (l == 0) out[(t + 1) * B + b] = ys0;

        // ---- U += sum_j d_j * W1col[j] + c  (16 independent broadcasts) ----
        const ull dsp = pk2(v[0], v[0]);     // (d_{l&15}, d_{l&15}) splat
        ull s0 = fma2(__shfl_sync(FULL_MASK, dsp, 0), w1c2[0], c2);
        ull s1 = mul2(__shfl_sync(FULL_MASK, dsp, 1), w1c2[1]);
        ull s2 = mul2(__shfl_sync(FULL_MASK, dsp, 2), w1c2[2]);
        ull s3 = mul2(__shfl_sync(FULL_MASK, dsp, 3), w1c2[3]);
#pragma unroll
        for (int j = 4; j < 16; j += 4) {
            s0 = fma2(__shfl_sync(FULL_MASK, dsp, j),     w1c2[j],     s0);
            s1 = fma2(__shfl_sync(FULL_MASK, dsp, j + 1), w1c2[j + 1], s1);
            s2 = fma2(__shfl_sync(FULL_MASK, dsp, j + 2), w1c2[j + 2], s2);
            s3 = fma2(__shfl_sync(FULL_MASK, dsp, j + 3), w1c2[j + 3], s3);
        }
        U2 = add2(U2, add2(add2(s0, s1), add2(s2, s3)));
    }
}

extern "C" void kernel_launch(void* const* d_in, const int* in_sizes, int n_in,
                              void* d_out, int out_size) {
    const float* x  = (const float*)d_in[0];
    const float* W1 = (const float*)d_in[1];
    const float* b1 = (const float*)d_in[2];
    const float* W2 = (const float*)d_in[3];
    const float* b2 = (const float*)d_in[4];
    float* out = (float*)d_out;

    const int T = in_sizes[0] / 32;   // x is (T, B=32, F=1)
    ode_fe_kernel<<<32, 32>>>(x, W1, b1, b2, W2, out, T);
}